// round 3
// baseline (speedup 1.0000x reference)
#include <cuda_runtime.h>
#include <cstdint>

// Problem constants (fixed per the reference)
constexpr int    NN = 50000;
constexpr long long EE = 1600000;
constexpr int    HH = 128;

// Scratch (device globals: allocation-free rule)
__device__ float g_attr[EE * 5];          // per-edge physics features
__device__ float g_h   [(size_t)NN * HH]; // node state
__device__ float g_AB  [(size_t)NN * 2 * HH]; // A = h@W1a (cols 0..127), B = h@W1b (cols 128..255)
__device__ float g_S   [(size_t)NN * HH]; // scatter accumulator of silu(ln(pre))
__device__ float g_deg [NN];
__device__ float g_aggr[(size_t)NN * HH];
__device__ float g_part[(size_t)NN * HH]; // h @ n_w1[:128]
__device__ float g_u   [(size_t)NN * HH]; // post-LN-SiLU node hidden
__device__ int   g_is64;

__device__ __forceinline__ float siluf(float v) { return v / (1.f + __expf(-v)); }

// Block-wide (128 threads) mean/var; all threads must call.
__device__ __forceinline__ float2 block_mean_var_128(float v, float* sred) {
    float s1 = v, s2 = v * v;
#pragma unroll
    for (int o = 16; o; o >>= 1) {
        s1 += __shfl_xor_sync(0xffffffffu, s1, o);
        s2 += __shfl_xor_sync(0xffffffffu, s2, o);
    }
    int w = threadIdx.x >> 5;
    if ((threadIdx.x & 31) == 0) { sred[2 * w] = s1; sred[2 * w + 1] = s2; }
    __syncthreads();
    float t1 = sred[0] + sred[2] + sred[4] + sred[6];
    float t2 = sred[1] + sred[3] + sred[5] + sred[7];
    __syncthreads();
    float m = t1 * (1.f / 128.f);
    return make_float2(m, t2 * (1.f / 128.f) - m * m);
}

// ---------- dtype detection for edge_index (int32 vs int64) ----------
__global__ void k_detect(const int* __restrict__ w, long long nwords) {
    __shared__ int s;
    if (threadIdx.x == 0) s = 0;
    __syncthreads();
    int any = 0;
    for (int i = threadIdx.x; i < 512; i += blockDim.x) {
        long long p = 2LL * i + 1;
        if (p < nwords && w[p] != 0) any = 1;
    }
    if (any) atomicOr(&s, 1);
    __syncthreads();
    if (threadIdx.x == 0) g_is64 = (s == 0) ? 1 : 0;
}

__device__ __forceinline__ void load_edge(const void* eidx, long long e, long long E, int& r, int& c) {
    if (g_is64) {
        const long long* p = (const long long*)eidx;
        r = (int)p[e]; c = (int)p[E + e];
    } else {
        const int* p = (const int*)eidx;
        r = p[e]; c = p[E + e];
    }
}

// ---------- edge physics features ----------
__global__ void k_attr(const void* __restrict__ eidx, const float* __restrict__ pos, long long E) {
    long long e = (long long)blockIdx.x * blockDim.x + threadIdx.x;
    if (e >= E) return;
    int r, c; load_edge(eidx, e, E, r, c);
    float dx = pos[(size_t)c * 3 + 0] - pos[(size_t)r * 3 + 0];
    float dy = pos[(size_t)c * 3 + 1] - pos[(size_t)r * 3 + 1];
    float dz = pos[(size_t)c * 3 + 2] - pos[(size_t)r * 3 + 2];
    float d = sqrtf(dx * dx + dy * dy + dz * dz) + 1e-8f;
    float inv = 1.f / d;
    g_attr[e * 5 + 0] = d;
    g_attr[e * 5 + 1] = dx * inv;
    g_attr[e * 5 + 2] = dy * inv;
    g_attr[e * 5 + 3] = dz * inv;
    g_attr[e * 5 + 4] = 1.f / (d * d + 1e-6f);
}

// ---------- encoder: h = (x@w1+b1 -> LN -> SiLU) @ w2 + b2 ----------
__global__ void k_encoder(const float* __restrict__ x,
                          const float* __restrict__ w1, const float* __restrict__ b1,
                          const float* __restrict__ g,  const float* __restrict__ be,
                          const float* __restrict__ w2, const float* __restrict__ b2, int N) {
    int t = threadIdx.x;
    float w1r[7];
#pragma unroll
    for (int k = 0; k < 7; k++) w1r[k] = w1[k * 128 + t];
    float w2r[128];
#pragma unroll
    for (int k = 0; k < 128; k++) w2r[k] = w2[k * 128 + t];
    float b1t = b1[t], gt = g[t], bet = be[t], b2t = b2[t];
    __shared__ float sx[8];
    __shared__ __align__(16) float ss[128];
    __shared__ float sred[8];
    for (int n = blockIdx.x; n < N; n += gridDim.x) {
        if (t < 7) sx[t] = x[(size_t)n * 7 + t];
        __syncthreads();
        float h1 = b1t;
#pragma unroll
        for (int k = 0; k < 7; k++) h1 = fmaf(sx[k], w1r[k], h1);
        float2 mv = block_mean_var_128(h1, sred);
        float v = (h1 - mv.x) * rsqrtf(mv.y + 1e-5f) * gt + bet;
        ss[t] = siluf(v);
        __syncthreads();
        float acc = b2t;
        const float4* s4 = (const float4*)ss;
#pragma unroll
        for (int k = 0; k < 32; k++) {
            float4 q = s4[k];
            acc = fmaf(q.x, w2r[4 * k + 0], acc);
            acc = fmaf(q.y, w2r[4 * k + 1], acc);
            acc = fmaf(q.z, w2r[4 * k + 2], acc);
            acc = fmaf(q.w, w2r[4 * k + 3], acc);
        }
        g_h[(size_t)n * 128 + t] = acc;
        __syncthreads();
    }
}

// ---------- zero S and deg ----------
__global__ void k_zero(int N) {
    long long tot = (long long)N * 128 + N;
    for (long long i = (long long)blockIdx.x * blockDim.x + threadIdx.x; i < tot;
         i += (long long)gridDim.x * blockDim.x) {
        if (i < (long long)N * 128) g_S[i] = 0.f;
        else g_deg[i - (long long)N * 128] = 0.f;
    }
}

// ---------- generic node GEMM (in: N x 128, W: 128 x 128 row-major), weights in registers ----------
// MODE 0: out[n*ostride+oofs+t] = acc
// MODE 1: out = acc + g_deg[n]*p1[t]                               (aggr epilogue)
// MODE 2: v = acc + g_part[n,t] + p1[t]; LN(p2,p3); silu -> out    (node hidden)
// MODE 3: v = g_h[n,t] + acc + p1[t];    LN(p2,p3)      -> out     (residual+LN, out==g_h)
template <int MODE>
__global__ void k_gemm(const float* __restrict__ in, const float* __restrict__ W,
                       float* __restrict__ out, int ostride, int oofs,
                       const float* __restrict__ p1, const float* __restrict__ p2,
                       const float* __restrict__ p3, int N) {
    int t = threadIdx.x;
    float w[128];
#pragma unroll
    for (int k = 0; k < 128; k++) w[k] = W[k * 128 + t];
    float e1 = 0.f, e2 = 0.f, e3 = 0.f;
    if constexpr (MODE == 1) { e1 = p1[t]; }
    if constexpr (MODE == 2 || MODE == 3) { e1 = p1[t]; e2 = p2[t]; e3 = p3[t]; }
    __shared__ __align__(16) float4 sin4[32];
    __shared__ float sred[8];
    for (int n = blockIdx.x; n < N; n += gridDim.x) {
        if (t < 32) sin4[t] = ((const float4*)(in + (size_t)n * 128))[t];
        __syncthreads();
        float acc = 0.f;
#pragma unroll
        for (int k = 0; k < 32; k++) {
            float4 q = sin4[k];
            acc = fmaf(q.x, w[4 * k + 0], acc);
            acc = fmaf(q.y, w[4 * k + 1], acc);
            acc = fmaf(q.z, w[4 * k + 2], acc);
            acc = fmaf(q.w, w[4 * k + 3], acc);
        }
        if constexpr (MODE == 0) {
            out[(size_t)n * ostride + oofs + t] = acc;
        } else if constexpr (MODE == 1) {
            out[(size_t)n * 128 + t] = acc + g_deg[n] * e1;
        } else if constexpr (MODE == 2) {
            float v = acc + g_part[(size_t)n * 128 + t] + e1;
            float2 mv = block_mean_var_128(v, sred);
            v = (v - mv.x) * rsqrtf(mv.y + 1e-5f) * e2 + e3;
            out[(size_t)n * 128 + t] = siluf(v);
        } else {
            float v = g_h[(size_t)n * 128 + t] + acc + e1;
            float2 mv = block_mean_var_128(v, sred);
            out[(size_t)n * 128 + t] = (v - mv.x) * rsqrtf(mv.y + 1e-5f) * e2 + e3;
        }
        __syncthreads();
    }
}

// ---------- edge kernel: pre = A[col]+B[row]+attr@W1attr+b1; LN; SiLU; scatter-add ----------
__global__ void k_edge(const void* __restrict__ eidx,
                       const float* __restrict__ w1attr, const float* __restrict__ b1,
                       const float* __restrict__ g, const float* __restrict__ be, long long E) {
    long long gw = ((long long)blockIdx.x * blockDim.x + threadIdx.x) >> 5;
    int lane = threadIdx.x & 31;
    if (gw >= E) return;
    long long e = gw;
    int r, c; load_edge(eidx, e, E, r, c);

    float4 a = ((const float4*)(g_AB + (size_t)c * 256))[lane];
    float4 b = ((const float4*)(g_AB + (size_t)r * 256 + 128))[lane];
    float4 bb = ((const float4*)b1)[lane];
    float4 acc;
    acc.x = a.x + b.x + bb.x; acc.y = a.y + b.y + bb.y;
    acc.z = a.z + b.z + bb.z; acc.w = a.w + b.w + bb.w;
#pragma unroll
    for (int k = 0; k < 5; k++) {
        float ak = __ldg(&g_attr[e * 5 + k]);
        float4 wk = ((const float4*)(w1attr + k * 128))[lane];
        acc.x = fmaf(ak, wk.x, acc.x); acc.y = fmaf(ak, wk.y, acc.y);
        acc.z = fmaf(ak, wk.z, acc.z); acc.w = fmaf(ak, wk.w, acc.w);
    }
    // LayerNorm over the 128 channels of this edge (warp-wide)
    float s1 = acc.x + acc.y + acc.z + acc.w;
    float s2 = fmaf(acc.x, acc.x, fmaf(acc.y, acc.y, fmaf(acc.z, acc.z, acc.w * acc.w)));
#pragma unroll
    for (int o = 16; o; o >>= 1) {
        s1 += __shfl_xor_sync(0xffffffffu, s1, o);
        s2 += __shfl_xor_sync(0xffffffffu, s2, o);
    }
    float m = s1 * (1.f / 128.f);
    float var = s2 * (1.f / 128.f) - m * m;
    float rstd = rsqrtf(var + 1e-5f);
    float4 gg = ((const float4*)g)[lane];
    float4 ee = ((const float4*)be)[lane];
    float4 sv;
    sv.x = siluf((acc.x - m) * rstd * gg.x + ee.x);
    sv.y = siluf((acc.y - m) * rstd * gg.y + ee.y);
    sv.z = siluf((acc.z - m) * rstd * gg.z + ee.z);
    sv.w = siluf((acc.w - m) * rstd * gg.w + ee.w);

    float* dst = g_S + (size_t)c * 128 + lane * 4;
    asm volatile("red.global.add.v4.f32 [%0], {%1, %2, %3, %4};"
                 :: "l"(dst), "f"(sv.x), "f"(sv.y), "f"(sv.z), "f"(sv.w) : "memory");
    if (lane == 0) atomicAdd(&g_deg[c], 1.0f);
}

// ---------- decoder: out = x[:, :6] + MLP(h) ----------
__global__ void k_decoder(const float* __restrict__ x,
                          const float* __restrict__ w1, const float* __restrict__ b1,
                          const float* __restrict__ w2, const float* __restrict__ b2,
                          const float* __restrict__ w3, const float* __restrict__ b3,
                          float* __restrict__ out, int N) {
    int t = threadIdx.x;
    float w1r[128];
#pragma unroll
    for (int k = 0; k < 128; k++) w1r[k] = w1[k * 128 + t];
    float b1t = b1[t];
    float b2t = (t < 64) ? b2[t] : 0.f;
    float b3t = (t < 6) ? b3[t] : 0.f;
    __shared__ __align__(16) float sh[128];
    __shared__ __align__(16) float sd1[128];
    __shared__ __align__(16) float sd2[64];
    __shared__ float sw2[128 * 64];
    __shared__ float sw3[64 * 6];
    for (int i = t; i < 128 * 64; i += blockDim.x) sw2[i] = w2[i];
    for (int i = t; i < 64 * 6; i += blockDim.x) sw3[i] = w3[i];
    __syncthreads();
    for (int n = blockIdx.x; n < N; n += gridDim.x) {
        sh[t] = g_h[(size_t)n * 128 + t];
        __syncthreads();
        float a1 = b1t;
        const float4* h4 = (const float4*)sh;
#pragma unroll
        for (int k = 0; k < 32; k++) {
            float4 q = h4[k];
            a1 = fmaf(q.x, w1r[4 * k + 0], a1);
            a1 = fmaf(q.y, w1r[4 * k + 1], a1);
            a1 = fmaf(q.z, w1r[4 * k + 2], a1);
            a1 = fmaf(q.w, w1r[4 * k + 3], a1);
        }
        sd1[t] = siluf(a1);
        __syncthreads();
        if (t < 64) {
            float a2 = b2t;
#pragma unroll
            for (int k = 0; k < 128; k++) a2 = fmaf(sd1[k], sw2[k * 64 + t], a2);
            sd2[t] = siluf(a2);
        }
        __syncthreads();
        if (t < 6) {
            float a3 = b3t;
#pragma unroll
            for (int k = 0; k < 64; k++) a3 = fmaf(sd2[k], sw3[k * 6 + t], a3);
            out[(size_t)n * 6 + t] = x[(size_t)n * 7 + t] + a3;
        }
        __syncthreads();
    }
}

extern "C" void kernel_launch(void* const* d_in, const int* in_sizes, int n_in,
                              void* d_out, int out_size) {
    const float* x      = (const float*)d_in[0];
    const float* pos    = (const float*)d_in[1];
    const void*  eidx   = d_in[2];
    const float* enc_w1 = (const float*)d_in[3];
    const float* enc_b1 = (const float*)d_in[4];
    const float* enc_g  = (const float*)d_in[5];
    const float* enc_be = (const float*)d_in[6];
    const float* enc_w2 = (const float*)d_in[7];
    const float* enc_b2 = (const float*)d_in[8];
    const float* e_w1   = (const float*)d_in[9];
    const float* e_b1   = (const float*)d_in[10];
    const float* e_g    = (const float*)d_in[11];
    const float* e_be   = (const float*)d_in[12];
    const float* e_w2   = (const float*)d_in[13];
    const float* e_b2   = (const float*)d_in[14];
    const float* n_w1   = (const float*)d_in[15];
    const float* n_b1   = (const float*)d_in[16];
    const float* n_g    = (const float*)d_in[17];
    const float* n_be   = (const float*)d_in[18];
    const float* n_w2   = (const float*)d_in[19];
    const float* n_b2   = (const float*)d_in[20];
    const float* ln_g   = (const float*)d_in[21];
    const float* ln_b   = (const float*)d_in[22];
    const float* dec_w1 = (const float*)d_in[23];
    const float* dec_b1 = (const float*)d_in[24];
    const float* dec_w2 = (const float*)d_in[25];
    const float* dec_b2 = (const float*)d_in[26];
    const float* dec_w3 = (const float*)d_in[27];
    const float* dec_b3 = (const float*)d_in[28];
    float* out = (float*)d_out;

    int N = in_sizes[0] / 7;
    long long E = (long long)in_sizes[2] / 2;

    float *p_h, *p_AB, *p_S, *p_aggr, *p_part, *p_u;
    cudaGetSymbolAddress((void**)&p_h,    g_h);
    cudaGetSymbolAddress((void**)&p_AB,   g_AB);
    cudaGetSymbolAddress((void**)&p_S,    g_S);
    cudaGetSymbolAddress((void**)&p_aggr, g_aggr);
    cudaGetSymbolAddress((void**)&p_part, g_part);
    cudaGetSymbolAddress((void**)&p_u,    g_u);

    const int GB = 1184;  // node-level grid (grid-stride)

    k_detect<<<1, 256>>>((const int*)eidx, 2 * E);
    k_attr<<<(unsigned)((E + 255) / 256), 256>>>(eidx, pos, E);
    k_encoder<<<GB, 128>>>(x, enc_w1, enc_b1, enc_g, enc_be, enc_w2, enc_b2, N);

    unsigned edgeGrid = (unsigned)((E + 7) / 8);  // 8 edges (warps) per 256-thread block
    for (int l = 0; l < 3; l++) {
        const float* W1 = e_w1 + (size_t)l * 261 * 128;
        k_zero<<<512, 256>>>(N);
        // A = h @ W1[0:128], B = h @ W1[128:256]  (into g_AB with stride 256)
        k_gemm<0><<<GB, 128>>>(p_h, W1,              p_AB, 256, 0,   nullptr, nullptr, nullptr, N);
        k_gemm<0><<<GB, 128>>>(p_h, W1 + 128 * 128,  p_AB, 256, 128, nullptr, nullptr, nullptr, N);
        // per-edge: pre->LN->SiLU, scatter into S/deg
        k_edge<<<edgeGrid, 256>>>(eidx, W1 + 256 * 128, e_b1 + l * 128,
                                  e_g + l * 128, e_be + l * 128, E);
        // aggr = S @ e_w2 + deg * e_b2
        k_gemm<1><<<GB, 128>>>(p_S, e_w2 + (size_t)l * 128 * 128, p_aggr, 128, 0,
                               e_b2 + l * 128, nullptr, nullptr, N);
        // node MLP: part = h @ n_w1[:128]; u = silu(ln(part + aggr @ n_w1[128:] + b1))
        k_gemm<0><<<GB, 128>>>(p_h, n_w1 + (size_t)l * 256 * 128, p_part, 128, 0,
                               nullptr, nullptr, nullptr, N);
        k_gemm<2><<<GB, 128>>>(p_aggr, n_w1 + (size_t)l * 256 * 128 + 128 * 128, p_u, 128, 0,
                               n_b1 + l * 128, n_g + l * 128, n_be + l * 128, N);
        // h = ln(h + u @ n_w2 + b2, ln_g, ln_b)
        k_gemm<3><<<GB, 128>>>(p_u, n_w2 + (size_t)l * 128 * 128, p_h, 128, 0,
                               n_b2 + l * 128, ln_g + l * 128, ln_b + l * 128, N);
    }

    k_decoder<<<GB, 128>>>(x, dec_w1, dec_b1, dec_w2, dec_b2, dec_w3, dec_b3, out, N);
}

// round 4
// speedup vs baseline: 1.0649x; 1.0649x over previous
#include <cuda_runtime.h>
#include <cstdint>

// Problem constants (fixed per the reference)
constexpr int    NN = 50000;
constexpr long long EE = 1600000;
constexpr int    HH = 128;

// Scratch (device globals: allocation-free rule)
__device__ float g_h   [(size_t)NN * HH]; // node state
__device__ float g_AB  [(size_t)NN * 2 * HH]; // A = h@W1a (cols 0..127), B = h@W1b (cols 128..255)
__device__ float g_S   [(size_t)NN * HH]; // segment-summed silu(ln(pre))
__device__ float g_aggr[(size_t)NN * HH];
__device__ float g_part[(size_t)NN * HH]; // h @ n_w1[:128]
__device__ float g_u   [(size_t)NN * HH]; // post-LN-SiLU node hidden
__device__ int   g_is64;

// Edge sort (by target node c)
__device__ int   g_cnt [NN + 1];
__device__ int   g_off [NN + 1];
__device__ int   g_cur [NN];
__device__ int   g_srcS[EE];              // sorted source index per edge
__device__ float g_attrS[EE * 5];         // sorted physics features per edge

__device__ __forceinline__ float siluf(float v) { return v / (1.f + __expf(-v)); }

// Block-wide (128 threads) mean/var; all threads must call.
__device__ __forceinline__ float2 block_mean_var_128(float v, float* sred) {
    float s1 = v, s2 = v * v;
#pragma unroll
    for (int o = 16; o; o >>= 1) {
        s1 += __shfl_xor_sync(0xffffffffu, s1, o);
        s2 += __shfl_xor_sync(0xffffffffu, s2, o);
    }
    int w = threadIdx.x >> 5;
    if ((threadIdx.x & 31) == 0) { sred[2 * w] = s1; sred[2 * w + 1] = s2; }
    __syncthreads();
    float t1 = sred[0] + sred[2] + sred[4] + sred[6];
    float t2 = sred[1] + sred[3] + sred[5] + sred[7];
    __syncthreads();
    float m = t1 * (1.f / 128.f);
    return make_float2(m, t2 * (1.f / 128.f) - m * m);
}

// ---------- dtype detection for edge_index (int32 vs int64) ----------
__global__ void k_detect(const int* __restrict__ w, long long nwords) {
    __shared__ int s;
    if (threadIdx.x == 0) s = 0;
    __syncthreads();
    int any = 0;
    for (int i = threadIdx.x; i < 512; i += blockDim.x) {
        long long p = 2LL * i + 1;
        if (p < nwords && w[p] != 0) any = 1;
    }
    if (any) atomicOr(&s, 1);
    __syncthreads();
    if (threadIdx.x == 0) g_is64 = (s == 0) ? 1 : 0;
}

__device__ __forceinline__ void load_edge(const void* eidx, long long e, long long E, int& r, int& c) {
    if (g_is64) {
        const long long* p = (const long long*)eidx;
        r = (int)p[e]; c = (int)p[E + e];
    } else {
        const int* p = (const int*)eidx;
        r = p[e]; c = p[E + e];
    }
}

// ---------- counting sort by target ----------
__global__ void k_zero_cnt(int N) {
    int i = blockIdx.x * blockDim.x + threadIdx.x;
    if (i <= N) g_cnt[i] = 0;
}

__global__ void k_hist(const void* __restrict__ eidx, long long E) {
    long long e = (long long)blockIdx.x * blockDim.x + threadIdx.x;
    if (e >= E) return;
    int r, c; load_edge(eidx, e, E, r, c);
    atomicAdd(&g_cnt[c], 1);
}

// single-block exclusive scan of g_cnt[0..N) -> g_off, g_cur; g_off[N] = total
__global__ void k_scan(int N) {
    __shared__ int sw[32];
    __shared__ int s_carry;
    int t = threadIdx.x;             // 1024 threads
    int lane = t & 31, wid = t >> 5;
    if (t == 0) s_carry = 0;
    __syncthreads();
    for (int base = 0; base < N; base += 1024) {
        int v = (base + t < N) ? g_cnt[base + t] : 0;
        int x = v;
#pragma unroll
        for (int o = 1; o < 32; o <<= 1) {
            int y = __shfl_up_sync(0xffffffffu, x, o);
            if (lane >= o) x += y;
        }
        if (lane == 31) sw[wid] = x;
        __syncthreads();
        if (wid == 0) {
            int y = sw[lane];
#pragma unroll
            for (int o = 1; o < 32; o <<= 1) {
                int z = __shfl_up_sync(0xffffffffu, y, o);
                if (lane >= o) y += z;
            }
            sw[lane] = y;
        }
        __syncthreads();
        int carry = s_carry;
        int incl = x + (wid ? sw[wid - 1] : 0);
        int excl = incl - v + carry;
        if (base + t < N) { g_off[base + t] = excl; g_cur[base + t] = excl; }
        int tot = sw[31];
        __syncthreads();
        if (t == 0) s_carry = carry + tot;
        __syncthreads();
    }
    if (t == 0) g_off[N] = s_carry;
}

// scatter edges into target-sorted order; compute physics features here
__global__ void k_scatter(const void* __restrict__ eidx, const float* __restrict__ pos, long long E) {
    long long e = (long long)blockIdx.x * blockDim.x + threadIdx.x;
    if (e >= E) return;
    int r, c; load_edge(eidx, e, E, r, c);
    float dx = pos[(size_t)c * 3 + 0] - pos[(size_t)r * 3 + 0];
    float dy = pos[(size_t)c * 3 + 1] - pos[(size_t)r * 3 + 1];
    float dz = pos[(size_t)c * 3 + 2] - pos[(size_t)r * 3 + 2];
    float d = sqrtf(dx * dx + dy * dy + dz * dz) + 1e-8f;
    float inv = 1.f / d;
    int p = atomicAdd(&g_cur[c], 1);
    g_srcS[p] = r;
    float* a = g_attrS + (size_t)p * 5;
    a[0] = d;
    a[1] = dx * inv;
    a[2] = dy * inv;
    a[3] = dz * inv;
    a[4] = 1.f / (d * d + 1e-6f);
}

// ---------- encoder: h = (x@w1+b1 -> LN -> SiLU) @ w2 + b2 ----------
__global__ void k_encoder(const float* __restrict__ x,
                          const float* __restrict__ w1, const float* __restrict__ b1,
                          const float* __restrict__ g,  const float* __restrict__ be,
                          const float* __restrict__ w2, const float* __restrict__ b2, int N) {
    int t = threadIdx.x;
    float w1r[7];
#pragma unroll
    for (int k = 0; k < 7; k++) w1r[k] = w1[k * 128 + t];
    float w2r[128];
#pragma unroll
    for (int k = 0; k < 128; k++) w2r[k] = w2[k * 128 + t];
    float b1t = b1[t], gt = g[t], bet = be[t], b2t = b2[t];
    __shared__ float sx[8];
    __shared__ __align__(16) float ss[128];
    __shared__ float sred[8];
    for (int n = blockIdx.x; n < N; n += gridDim.x) {
        if (t < 7) sx[t] = x[(size_t)n * 7 + t];
        __syncthreads();
        float h1 = b1t;
#pragma unroll
        for (int k = 0; k < 7; k++) h1 = fmaf(sx[k], w1r[k], h1);
        float2 mv = block_mean_var_128(h1, sred);
        float v = (h1 - mv.x) * rsqrtf(mv.y + 1e-5f) * gt + bet;
        ss[t] = siluf(v);
        __syncthreads();
        float acc = b2t;
        const float4* s4 = (const float4*)ss;
#pragma unroll
        for (int k = 0; k < 32; k++) {
            float4 q = s4[k];
            acc = fmaf(q.x, w2r[4 * k + 0], acc);
            acc = fmaf(q.y, w2r[4 * k + 1], acc);
            acc = fmaf(q.z, w2r[4 * k + 2], acc);
            acc = fmaf(q.w, w2r[4 * k + 3], acc);
        }
        g_h[(size_t)n * 128 + t] = acc;
        __syncthreads();
    }
}

// ---------- generic node GEMM (in: N x 128, W: 128 x 128 row-major), weights in registers ----------
// MODE 0: out[n*ostride+oofs+t] = acc
// MODE 1: out = acc + deg(n)*p1[t]                                 (aggr epilogue)
// MODE 2: v = acc + g_part[n,t] + p1[t]; LN(p2,p3); silu -> out    (node hidden)
// MODE 3: v = g_h[n,t] + acc + p1[t];    LN(p2,p3)      -> out     (residual+LN, out==g_h)
template <int MODE>
__global__ void k_gemm(const float* __restrict__ in, const float* __restrict__ W,
                       float* __restrict__ out, int ostride, int oofs,
                       const float* __restrict__ p1, const float* __restrict__ p2,
                       const float* __restrict__ p3, int N) {
    int t = threadIdx.x;
    float w[128];
#pragma unroll
    for (int k = 0; k < 128; k++) w[k] = W[k * 128 + t];
    float e1 = 0.f, e2 = 0.f, e3 = 0.f;
    if constexpr (MODE == 1) { e1 = p1[t]; }
    if constexpr (MODE == 2 || MODE == 3) { e1 = p1[t]; e2 = p2[t]; e3 = p3[t]; }
    __shared__ __align__(16) float4 sin4[32];
    __shared__ float sred[8];
    for (int n = blockIdx.x; n < N; n += gridDim.x) {
        if (t < 32) sin4[t] = ((const float4*)(in + (size_t)n * 128))[t];
        __syncthreads();
        float acc = 0.f;
#pragma unroll
        for (int k = 0; k < 32; k++) {
            float4 q = sin4[k];
            acc = fmaf(q.x, w[4 * k + 0], acc);
            acc = fmaf(q.y, w[4 * k + 1], acc);
            acc = fmaf(q.z, w[4 * k + 2], acc);
            acc = fmaf(q.w, w[4 * k + 3], acc);
        }
        if constexpr (MODE == 0) {
            out[(size_t)n * ostride + oofs + t] = acc;
        } else if constexpr (MODE == 1) {
            float deg = (float)(g_off[n + 1] - g_off[n]);
            out[(size_t)n * 128 + t] = acc + deg * e1;
        } else if constexpr (MODE == 2) {
            float v = acc + g_part[(size_t)n * 128 + t] + e1;
            float2 mv = block_mean_var_128(v, sred);
            v = (v - mv.x) * rsqrtf(mv.y + 1e-5f) * e2 + e3;
            out[(size_t)n * 128 + t] = siluf(v);
        } else {
            float v = g_h[(size_t)n * 128 + t] + acc + e1;
            float2 mv = block_mean_var_128(v, sred);
            out[(size_t)n * 128 + t] = (v - mv.x) * rsqrtf(mv.y + 1e-5f) * e2 + e3;
        }
        __syncthreads();
    }
}

// ---------- edge aggregation: one warp per target node, atomic-free ----------
// S[n] = sum over edges e->n of silu(ln(A[n] + B[src(e)] + attr(e)@Wattr + b1))
__global__ void k_edge_agg(const float* __restrict__ w1attr, const float* __restrict__ b1,
                           const float* __restrict__ g, const float* __restrict__ be, int N) {
    int warp = (blockIdx.x * blockDim.x + threadIdx.x) >> 5;
    int lane = threadIdx.x & 31;
    if (warp >= N) return;
    int n = warp;
    int s0 = g_off[n], s1 = g_off[n + 1];

    float4 a4 = ((const float4*)(g_AB + (size_t)n * 256))[lane];
    float4 bb = ((const float4*)b1)[lane];
    float4 base = make_float4(a4.x + bb.x, a4.y + bb.y, a4.z + bb.z, a4.w + bb.w);
    float4 gg = ((const float4*)g)[lane];
    float4 ee = ((const float4*)be)[lane];
    float4 w0 = ((const float4*)(w1attr + 0 * 128))[lane];
    float4 w1 = ((const float4*)(w1attr + 1 * 128))[lane];
    float4 w2 = ((const float4*)(w1attr + 2 * 128))[lane];
    float4 w3 = ((const float4*)(w1attr + 3 * 128))[lane];
    float4 w4 = ((const float4*)(w1attr + 4 * 128))[lane];

    float4 acc = make_float4(0.f, 0.f, 0.f, 0.f);

    float4 bn = make_float4(0.f, 0.f, 0.f, 0.f);
    float at0 = 0.f, at1 = 0.f, at2 = 0.f, at3 = 0.f, at4 = 0.f;
    if (s0 < s1) {
        int r = __ldg(&g_srcS[s0]);
        bn = __ldg(((const float4*)(g_AB + (size_t)r * 256 + 128)) + lane);
        const float* ap = g_attrS + (size_t)s0 * 5;
        at0 = __ldg(ap + 0); at1 = __ldg(ap + 1); at2 = __ldg(ap + 2);
        at3 = __ldg(ap + 3); at4 = __ldg(ap + 4);
    }
    for (int i = s0; i < s1; i++) {
        float4 b = bn;
        float c0 = at0, c1 = at1, c2 = at2, c3 = at3, c4 = at4;
        if (i + 1 < s1) {
            int r = __ldg(&g_srcS[i + 1]);
            bn = __ldg(((const float4*)(g_AB + (size_t)r * 256 + 128)) + lane);
            const float* ap = g_attrS + (size_t)(i + 1) * 5;
            at0 = __ldg(ap + 0); at1 = __ldg(ap + 1); at2 = __ldg(ap + 2);
            at3 = __ldg(ap + 3); at4 = __ldg(ap + 4);
        }
        float4 pre;
        pre.x = base.x + b.x; pre.y = base.y + b.y;
        pre.z = base.z + b.z; pre.w = base.w + b.w;
        pre.x = fmaf(c0, w0.x, pre.x); pre.y = fmaf(c0, w0.y, pre.y);
        pre.z = fmaf(c0, w0.z, pre.z); pre.w = fmaf(c0, w0.w, pre.w);
        pre.x = fmaf(c1, w1.x, pre.x); pre.y = fmaf(c1, w1.y, pre.y);
        pre.z = fmaf(c1, w1.z, pre.z); pre.w = fmaf(c1, w1.w, pre.w);
        pre.x = fmaf(c2, w2.x, pre.x); pre.y = fmaf(c2, w2.y, pre.y);
        pre.z = fmaf(c2, w2.z, pre.z); pre.w = fmaf(c2, w2.w, pre.w);
        pre.x = fmaf(c3, w3.x, pre.x); pre.y = fmaf(c3, w3.y, pre.y);
        pre.z = fmaf(c3, w3.z, pre.z); pre.w = fmaf(c3, w3.w, pre.w);
        pre.x = fmaf(c4, w4.x, pre.x); pre.y = fmaf(c4, w4.y, pre.y);
        pre.z = fmaf(c4, w4.z, pre.z); pre.w = fmaf(c4, w4.w, pre.w);
        // warp LayerNorm over 128 channels
        float s1r = pre.x + pre.y + pre.z + pre.w;
        float s2r = fmaf(pre.x, pre.x, fmaf(pre.y, pre.y, fmaf(pre.z, pre.z, pre.w * pre.w)));
#pragma unroll
        for (int o = 16; o; o >>= 1) {
            s1r += __shfl_xor_sync(0xffffffffu, s1r, o);
            s2r += __shfl_xor_sync(0xffffffffu, s2r, o);
        }
        float m = s1r * (1.f / 128.f);
        float var = s2r * (1.f / 128.f) - m * m;
        float rstd = rsqrtf(var + 1e-5f);
        acc.x += siluf((pre.x - m) * rstd * gg.x + ee.x);
        acc.y += siluf((pre.y - m) * rstd * gg.y + ee.y);
        acc.z += siluf((pre.z - m) * rstd * gg.z + ee.z);
        acc.w += siluf((pre.w - m) * rstd * gg.w + ee.w);
    }
    ((float4*)(g_S + (size_t)n * 128))[lane] = acc;
}

// ---------- decoder: out = x[:, :6] + MLP(h) ----------
__global__ void k_decoder(const float* __restrict__ x,
                          const float* __restrict__ w1, const float* __restrict__ b1,
                          const float* __restrict__ w2, const float* __restrict__ b2,
                          const float* __restrict__ w3, const float* __restrict__ b3,
                          float* __restrict__ out, int N) {
    int t = threadIdx.x;
    float w1r[128];
#pragma unroll
    for (int k = 0; k < 128; k++) w1r[k] = w1[k * 128 + t];
    float b1t = b1[t];
    float b2t = (t < 64) ? b2[t] : 0.f;
    float b3t = (t < 6) ? b3[t] : 0.f;
    __shared__ __align__(16) float sh[128];
    __shared__ __align__(16) float sd1[128];
    __shared__ __align__(16) float sd2[64];
    __shared__ float sw2[128 * 64];
    __shared__ float sw3[64 * 6];
    for (int i = t; i < 128 * 64; i += blockDim.x) sw2[i] = w2[i];
    for (int i = t; i < 64 * 6; i += blockDim.x) sw3[i] = w3[i];
    __syncthreads();
    for (int n = blockIdx.x; n < N; n += gridDim.x) {
        sh[t] = g_h[(size_t)n * 128 + t];
        __syncthreads();
        float a1 = b1t;
        const float4* h4 = (const float4*)sh;
#pragma unroll
        for (int k = 0; k < 32; k++) {
            float4 q = h4[k];
            a1 = fmaf(q.x, w1r[4 * k + 0], a1);
            a1 = fmaf(q.y, w1r[4 * k + 1], a1);
            a1 = fmaf(q.z, w1r[4 * k + 2], a1);
            a1 = fmaf(q.w, w1r[4 * k + 3], a1);
        }
        sd1[t] = siluf(a1);
        __syncthreads();
        if (t < 64) {
            float a2 = b2t;
#pragma unroll
            for (int k = 0; k < 128; k++) a2 = fmaf(sd1[k], sw2[k * 64 + t], a2);
            sd2[t] = siluf(a2);
        }
        __syncthreads();
        if (t < 6) {
            float a3 = b3t;
#pragma unroll
            for (int k = 0; k < 64; k++) a3 = fmaf(sd2[k], sw3[k * 6 + t], a3);
            out[(size_t)n * 6 + t] = x[(size_t)n * 7 + t] + a3;
        }
        __syncthreads();
    }
}

extern "C" void kernel_launch(void* const* d_in, const int* in_sizes, int n_in,
                              void* d_out, int out_size) {
    const float* x      = (const float*)d_in[0];
    const float* pos    = (const float*)d_in[1];
    const void*  eidx   = d_in[2];
    const float* enc_w1 = (const float*)d_in[3];
    const float* enc_b1 = (const float*)d_in[4];
    const float* enc_g  = (const float*)d_in[5];
    const float* enc_be = (const float*)d_in[6];
    const float* enc_w2 = (const float*)d_in[7];
    const float* enc_b2 = (const float*)d_in[8];
    const float* e_w1   = (const float*)d_in[9];
    const float* e_b1   = (const float*)d_in[10];
    const float* e_g    = (const float*)d_in[11];
    const float* e_be   = (const float*)d_in[12];
    const float* e_w2   = (const float*)d_in[13];
    const float* e_b2   = (const float*)d_in[14];
    const float* n_w1   = (const float*)d_in[15];
    const float* n_b1   = (const float*)d_in[16];
    const float* n_g    = (const float*)d_in[17];
    const float* n_be   = (const float*)d_in[18];
    const float* n_w2   = (const float*)d_in[19];
    const float* n_b2   = (const float*)d_in[20];
    const float* ln_g   = (const float*)d_in[21];
    const float* ln_b   = (const float*)d_in[22];
    const float* dec_w1 = (const float*)d_in[23];
    const float* dec_b1 = (const float*)d_in[24];
    const float* dec_w2 = (const float*)d_in[25];
    const float* dec_b2 = (const float*)d_in[26];
    const float* dec_w3 = (const float*)d_in[27];
    const float* dec_b3 = (const float*)d_in[28];
    float* out = (float*)d_out;

    int N = in_sizes[0] / 7;
    long long E = (long long)in_sizes[2] / 2;

    float *p_h, *p_AB, *p_S, *p_aggr, *p_part, *p_u;
    cudaGetSymbolAddress((void**)&p_h,    g_h);
    cudaGetSymbolAddress((void**)&p_AB,   g_AB);
    cudaGetSymbolAddress((void**)&p_S,    g_S);
    cudaGetSymbolAddress((void**)&p_aggr, g_aggr);
    cudaGetSymbolAddress((void**)&p_part, g_part);
    cudaGetSymbolAddress((void**)&p_u,    g_u);

    const int GB = 1184;  // node-level grid (grid-stride)
    unsigned eg = (unsigned)((E + 255) / 256);

    // dtype detect + counting sort of edges by target + physics features
    k_detect<<<1, 256>>>((const int*)eidx, 2 * E);
    k_zero_cnt<<<(N + 256) / 256, 256>>>(N);
    k_hist<<<eg, 256>>>(eidx, E);
    k_scan<<<1, 1024>>>(N);
    k_scatter<<<eg, 256>>>(eidx, pos, E);

    k_encoder<<<GB, 128>>>(x, enc_w1, enc_b1, enc_g, enc_be, enc_w2, enc_b2, N);

    unsigned aggGrid = (unsigned)((N + 7) / 8);  // one warp per node, 256-thread blocks
    for (int l = 0; l < 3; l++) {
        const float* W1 = e_w1 + (size_t)l * 261 * 128;
        // A = h @ W1[0:128], B = h @ W1[128:256]  (into g_AB with stride 256)
        k_gemm<0><<<GB, 128>>>(p_h, W1,              p_AB, 256, 0,   nullptr, nullptr, nullptr, N);
        k_gemm<0><<<GB, 128>>>(p_h, W1 + 128 * 128,  p_AB, 256, 128, nullptr, nullptr, nullptr, N);
        // per-target segment aggregation (atomic-free)
        k_edge_agg<<<aggGrid, 256>>>(W1 + 256 * 128, e_b1 + l * 128,
                                     e_g + l * 128, e_be + l * 128, N);
        // aggr = S @ e_w2 + deg * e_b2
        k_gemm<1><<<GB, 128>>>(p_S, e_w2 + (size_t)l * 128 * 128, p_aggr, 128, 0,
                               e_b2 + l * 128, nullptr, nullptr, N);
        // node MLP: part = h @ n_w1[:128]; u = silu(ln(part + aggr @ n_w1[128:] + b1))
        k_gemm<0><<<GB, 128>>>(p_h, n_w1 + (size_t)l * 256 * 128, p_part, 128, 0,
                               nullptr, nullptr, nullptr, N);
        k_gemm<2><<<GB, 128>>>(p_aggr, n_w1 + (size_t)l * 256 * 128 + 128 * 128, p_u, 128, 0,
                               n_b1 + l * 128, n_g + l * 128, n_be + l * 128, N);
        // h = ln(h + u @ n_w2 + b2, ln_g, ln_b)
        k_gemm<3><<<GB, 128>>>(p_u, n_w2 + (size_t)l * 128 * 128, p_h, 128, 0,
                               n_b2 + l * 128, ln_g + l * 128, ln_b + l * 128, N);
    }

    k_decoder<<<GB, 128>>>(x, dec_w1, dec_b1, dec_w2, dec_b2, dec_w3, dec_b3, out, N);
}

// round 5
// speedup vs baseline: 1.4410x; 1.3532x over previous
#include <cuda_runtime.h>
#include <cstdint>

typedef unsigned long long u64;

// Problem constants (fixed per the reference)
constexpr int    NN = 50000;
constexpr long long EE = 1600000;
constexpr int    HH = 128;

// Scratch (device globals: allocation-free rule)
__device__ float g_h   [(size_t)NN * HH];
__device__ float g_AB  [(size_t)NN * 2 * HH]; // A cols 0..127, B cols 128..255
__device__ float g_S   [(size_t)NN * HH];
__device__ float g_aggr[(size_t)NN * HH];
__device__ float g_part[(size_t)NN * HH];
__device__ float g_u   [(size_t)NN * HH];
__device__ int   g_is64;

// Edge sort (by target node c)
__device__ int    g_cnt [NN + 1];
__device__ int    g_off [NN + 1];
__device__ int    g_cur [NN];
__device__ int    g_blk [66];
__device__ int    g_srcS[EE];
__device__ float4 g_attr4[EE];
__device__ float  g_attr1[EE];

// ---------- packed f32x2 helpers ----------
__device__ __forceinline__ u64 pk(float lo, float hi) {
    u64 r; asm("mov.b64 %0,{%1,%2};" : "=l"(r) : "f"(lo), "f"(hi)); return r;
}
__device__ __forceinline__ float2 upk(u64 v) {
    float2 q; asm("mov.b64 {%0,%1},%2;" : "=f"(q.x), "=f"(q.y) : "l"(v)); return q;
}
__device__ __forceinline__ u64 ffma2(u64 a, u64 b, u64 c) {
    u64 d; asm("fma.rn.f32x2 %0,%1,%2,%3;" : "=l"(d) : "l"(a), "l"(b), "l"(c)); return d;
}
__device__ __forceinline__ u64 fadd2(u64 a, u64 b) {
    u64 d; asm("add.rn.f32x2 %0,%1,%2;" : "=l"(d) : "l"(a), "l"(b)); return d;
}
__device__ __forceinline__ u64 fmul2(u64 a, u64 b) {
    u64 d; asm("mul.rn.f32x2 %0,%1,%2;" : "=l"(d) : "l"(a), "l"(b)); return d;
}

// silu via tanh.approx (1 MUFU instead of EX2+RCP):
// silu(x) = x*sigmoid(x) = 0.5x*tanh(0.5x) + 0.5x
__device__ __forceinline__ float siluf(float v) {
    float hx = 0.5f * v, t;
    asm("tanh.approx.f32 %0, %1;" : "=f"(t) : "f"(hx));
    return fmaf(hx, t, hx);
}

// ---------- dtype detection for edge_index (int32 vs int64) ----------
__global__ void k_detect(const int* __restrict__ w, long long nwords) {
    __shared__ int s;
    if (threadIdx.x == 0) s = 0;
    __syncthreads();
    int any = 0;
    for (int i = threadIdx.x; i < 512; i += blockDim.x) {
        long long p = 2LL * i + 1;
        if (p < nwords && w[p] != 0) any = 1;
    }
    if (any) atomicOr(&s, 1);
    __syncthreads();
    if (threadIdx.x == 0) g_is64 = (s == 0) ? 1 : 0;
}

__device__ __forceinline__ void load_edge(const void* eidx, long long e, long long E, int& r, int& c) {
    if (g_is64) {
        const long long* p = (const long long*)eidx;
        r = (int)p[e]; c = (int)p[E + e];
    } else {
        const int* p = (const int*)eidx;
        r = p[e]; c = p[E + e];
    }
}

// ---------- counting sort by target ----------
__global__ void k_zero_cnt(int N) {
    int i = blockIdx.x * blockDim.x + threadIdx.x;
    if (i <= N) g_cnt[i] = 0;
}

__global__ void k_hist(const void* __restrict__ eidx, long long E) {
    long long e = (long long)blockIdx.x * blockDim.x + threadIdx.x;
    if (e >= E) return;
    int r, c; load_edge(eidx, e, E, r, c);
    atomicAdd(&g_cnt[c], 1);
}

// Phase A: per-1024-chunk sums (grid = nchunks, 256 thr)
__global__ void k_scanA(int N) {
    __shared__ int sw[8];
    int b = blockIdx.x, t = threadIdx.x;
    int base = b * 1024;
    int s = 0;
    for (int i = t; i < 1024; i += 256) {
        int idx = base + i;
        s += (idx < N) ? g_cnt[idx] : 0;
    }
#pragma unroll
    for (int o = 16; o; o >>= 1) s += __shfl_xor_sync(0xffffffffu, s, o);
    if ((t & 31) == 0) sw[t >> 5] = s;
    __syncthreads();
    if (t == 0) {
        int tot = 0;
#pragma unroll
        for (int i = 0; i < 8; i++) tot += sw[i];
        g_blk[b] = tot;
    }
}

// Phase B: exclusive scan of chunk sums (1 block; nb <= 64)
__global__ void k_scanB(int nb) {
    __shared__ int sv[66];
    int t = threadIdx.x; // 64 threads
    if (t < nb) sv[t] = g_blk[t];
    __syncthreads();
    if (t == 0) {
        int run = 0;
        for (int i = 0; i < nb; i++) { int c = sv[i]; sv[i] = run; run += c; }
        sv[nb] = run;
    }
    __syncthreads();
    if (t <= nb) g_blk[t] = sv[t];
}

// Phase C: full exclusive scan per chunk + chunk offset (grid = nchunks, 1024 thr)
__global__ void k_scanC(int N, int nchunks) {
    __shared__ int sw[32];
    int b = blockIdx.x, t = threadIdx.x;
    int lane = t & 31, wid = t >> 5;
    int idx = b * 1024 + t;
    int v = (idx < N) ? g_cnt[idx] : 0;
    int x = v;
#pragma unroll
    for (int o = 1; o < 32; o <<= 1) {
        int y = __shfl_up_sync(0xffffffffu, x, o);
        if (lane >= o) x += y;
    }
    if (lane == 31) sw[wid] = x;
    __syncthreads();
    if (wid == 0) {
        int y = sw[lane];
#pragma unroll
        for (int o = 1; o < 32; o <<= 1) {
            int z = __shfl_up_sync(0xffffffffu, y, o);
            if (lane >= o) y += z;
        }
        sw[lane] = y;
    }
    __syncthreads();
    int excl = x - v + (wid ? sw[wid - 1] : 0) + g_blk[b];
    if (idx < N) { g_off[idx] = excl; g_cur[idx] = excl; }
    if (b == 0 && t == 0) g_off[N] = g_blk[nchunks];
}

// scatter edges into target-sorted order; compute physics features here
__global__ void k_scatter(const void* __restrict__ eidx, const float* __restrict__ pos, long long E) {
    long long e = (long long)blockIdx.x * blockDim.x + threadIdx.x;
    if (e >= E) return;
    int r, c; load_edge(eidx, e, E, r, c);
    float dx = pos[(size_t)c * 3 + 0] - pos[(size_t)r * 3 + 0];
    float dy = pos[(size_t)c * 3 + 1] - pos[(size_t)r * 3 + 1];
    float dz = pos[(size_t)c * 3 + 2] - pos[(size_t)r * 3 + 2];
    float d = sqrtf(dx * dx + dy * dy + dz * dz) + 1e-8f;
    float inv = 1.f / d;
    int p = atomicAdd(&g_cur[c], 1);
    g_srcS[p]  = r;
    g_attr4[p] = make_float4(d, dx * inv, dy * inv, dz * inv);
    g_attr1[p] = 1.f / (d * d + 1e-6f);
}

// ---------- encoder: h = (x@w1+b1 -> LN -> SiLU) @ w2 + b2 ----------
__global__ void k_encoder(const float* __restrict__ x,
                          const float* __restrict__ w1, const float* __restrict__ b1,
                          const float* __restrict__ g,  const float* __restrict__ be,
                          const float* __restrict__ w2, const float* __restrict__ b2, int N) {
    int t = threadIdx.x;
    float w1r[7];
#pragma unroll
    for (int k = 0; k < 7; k++) w1r[k] = w1[k * 128 + t];
    u64 w2p[64];
#pragma unroll
    for (int j = 0; j < 64; j++) w2p[j] = pk(w2[(2 * j) * 128 + t], w2[(2 * j + 1) * 128 + t]);
    float b1t = b1[t], gt = g[t], bet = be[t], b2t = b2[t];
    __shared__ float sx[8];
    __shared__ __align__(16) float ss[128];
    __shared__ float sred[8];
    for (int n = blockIdx.x; n < N; n += gridDim.x) {
        if (t < 7) sx[t] = x[(size_t)n * 7 + t];
        __syncthreads();
        float h1 = b1t;
#pragma unroll
        for (int k = 0; k < 7; k++) h1 = fmaf(sx[k], w1r[k], h1);
        // block LN
        float s1 = h1, s2 = h1 * h1;
#pragma unroll
        for (int o = 16; o; o >>= 1) {
            s1 += __shfl_xor_sync(0xffffffffu, s1, o);
            s2 += __shfl_xor_sync(0xffffffffu, s2, o);
        }
        int w = t >> 5;
        if ((t & 31) == 0) { sred[2 * w] = s1; sred[2 * w + 1] = s2; }
        __syncthreads();
        float t1 = sred[0] + sred[2] + sred[4] + sred[6];
        float t2 = sred[1] + sred[3] + sred[5] + sred[7];
        float m = t1 * (1.f / 128.f);
        float var = t2 * (1.f / 128.f) - m * m;
        float v = (h1 - m) * rsqrtf(var + 1e-5f) * gt + bet;
        ss[t] = siluf(v);
        __syncthreads();
        u64 a0 = 0, a1 = 0;
        const ulonglong2* s2p = (const ulonglong2*)ss;
#pragma unroll
        for (int k = 0; k < 32; k++) {
            ulonglong2 q = s2p[k];
            a0 = ffma2(q.x, w2p[2 * k],     a0);
            a1 = ffma2(q.y, w2p[2 * k + 1], a1);
        }
        float2 f0 = upk(a0), f1 = upk(a1);
        g_h[(size_t)n * 128 + t] = b2t + (f0.x + f0.y) + (f1.x + f1.y);
        __syncthreads();
    }
}

// ---------- batched block LN helper: 4 nodes at once, one barrier ----------
__device__ __forceinline__ void block_mv4(const float* vv, float2* mv, float* sred, int tid) {
    float s1[4], s2[4];
#pragma unroll
    for (int j = 0; j < 4; j++) { s1[j] = vv[j]; s2[j] = vv[j] * vv[j]; }
#pragma unroll
    for (int o = 16; o; o >>= 1) {
#pragma unroll
        for (int j = 0; j < 4; j++) {
            s1[j] += __shfl_xor_sync(0xffffffffu, s1[j], o);
            s2[j] += __shfl_xor_sync(0xffffffffu, s2[j], o);
        }
    }
    int w = tid >> 5;
    if ((tid & 31) == 0) {
#pragma unroll
        for (int j = 0; j < 4; j++) { sred[w * 8 + j * 2] = s1[j]; sred[w * 8 + j * 2 + 1] = s2[j]; }
    }
    __syncthreads();
#pragma unroll
    for (int j = 0; j < 4; j++) {
        float t1 = sred[j * 2] + sred[8 + j * 2] + sred[16 + j * 2] + sred[24 + j * 2];
        float t2 = sred[j * 2 + 1] + sred[8 + j * 2 + 1] + sred[16 + j * 2 + 1] + sred[24 + j * 2 + 1];
        float m = t1 * (1.f / 128.f);
        mv[j] = make_float2(m, t2 * (1.f / 128.f) - m * m);
    }
}

// ---------- node GEMM: f32x2, 4 nodes per iteration, weights in registers ----------
// MODE 0: out[n*ostride+oofs+t] = acc
// MODE 1: out = acc + deg(n)*p1[t]
// MODE 2: v = acc + g_part[n,t] + p1[t]; LN(p2,p3); silu -> out
// MODE 3: v = g_h[n,t] + acc + p1[t];    LN(p2,p3)      -> out
template <int MODE>
__global__ void k_gemm(const float* __restrict__ in, const float* __restrict__ W,
                       float* __restrict__ out, int ostride, int oofs,
                       const float* __restrict__ p1, const float* __restrict__ p2,
                       const float* __restrict__ p3, int N) {
    int t = threadIdx.x;
    u64 w[64];
#pragma unroll
    for (int j = 0; j < 64; j++) w[j] = pk(W[(2 * j) * 128 + t], W[(2 * j + 1) * 128 + t]);
    float e1 = 0.f, e2 = 0.f, e3 = 0.f;
    if constexpr (MODE == 1) { e1 = p1[t]; }
    if constexpr (MODE == 2 || MODE == 3) { e1 = p1[t]; e2 = p2[t]; e3 = p3[t]; }
    __shared__ __align__(16) float ss[4 * 128];
    __shared__ float sred[32];
    for (int n0 = blockIdx.x * 4; n0 < N; n0 += gridDim.x * 4) {
        int nodes = min(4, N - n0);
        if (t < nodes * 32) ((float4*)ss)[t] = ((const float4*)(in + (size_t)n0 * 128))[t];
        __syncthreads();
        float v[4];
#pragma unroll
        for (int j = 0; j < 4; j++) {
            u64 a0 = 0, a1 = 0;
            const ulonglong2* s2p = (const ulonglong2*)(ss + j * 128);
#pragma unroll
            for (int k = 0; k < 32; k++) {
                ulonglong2 q = s2p[k];
                a0 = ffma2(q.x, w[2 * k],     a0);
                a1 = ffma2(q.y, w[2 * k + 1], a1);
            }
            float2 f0 = upk(a0), f1 = upk(a1);
            v[j] = (f0.x + f0.y) + (f1.x + f1.y);
        }
        if constexpr (MODE == 0) {
            for (int j = 0; j < nodes; j++)
                out[(size_t)(n0 + j) * ostride + oofs + t] = v[j];
        } else if constexpr (MODE == 1) {
            for (int j = 0; j < nodes; j++) {
                float deg = (float)(g_off[n0 + j + 1] - g_off[n0 + j]);
                out[(size_t)(n0 + j) * 128 + t] = v[j] + deg * e1;
            }
        } else if constexpr (MODE == 2) {
            float vv[4];
#pragma unroll
            for (int j = 0; j < 4; j++)
                vv[j] = (j < nodes) ? (v[j] + g_part[(size_t)(n0 + j) * 128 + t] + e1) : 0.f;
            float2 mv[4];
            block_mv4(vv, mv, sred, t);
            for (int j = 0; j < nodes; j++) {
                float nv = (vv[j] - mv[j].x) * rsqrtf(mv[j].y + 1e-5f) * e2 + e3;
                out[(size_t)(n0 + j) * 128 + t] = siluf(nv);
            }
        } else {
            float vv[4];
#pragma unroll
            for (int j = 0; j < 4; j++)
                vv[j] = (j < nodes) ? (g_h[(size_t)(n0 + j) * 128 + t] + v[j] + e1) : 0.f;
            float2 mv[4];
            block_mv4(vv, mv, sred, t);
            for (int j = 0; j < nodes; j++) {
                float nv = (vv[j] - mv[j].x) * rsqrtf(mv[j].y + 1e-5f) * e2 + e3;
                out[(size_t)(n0 + j) * 128 + t] = nv;
            }
        }
        __syncthreads();
    }
}

// ---------- fused A/B projection: 256 threads; t<128 -> A col t, t>=128 -> B col (t-128) ----------
__global__ void k_gemmAB(const float* __restrict__ in, const float* __restrict__ W,
                         float* __restrict__ out, int N) {
    int t = threadIdx.x;          // 0..255
    int col = t & 127;
    const float* Wb = W + (size_t)(t >> 7) * 128 * 128;
    u64 w[64];
#pragma unroll
    for (int j = 0; j < 64; j++) w[j] = pk(Wb[(2 * j) * 128 + col], Wb[(2 * j + 1) * 128 + col]);
    __shared__ __align__(16) float ss[4 * 128];
    for (int n0 = blockIdx.x * 4; n0 < N; n0 += gridDim.x * 4) {
        int nodes = min(4, N - n0);
        if (t < nodes * 32) ((float4*)ss)[t] = ((const float4*)(in + (size_t)n0 * 128))[t];
        __syncthreads();
#pragma unroll
        for (int j = 0; j < 4; j++) {
            if (j >= nodes) break;
            u64 a0 = 0, a1 = 0;
            const ulonglong2* s2p = (const ulonglong2*)(ss + j * 128);
#pragma unroll
            for (int k = 0; k < 32; k++) {
                ulonglong2 q = s2p[k];
                a0 = ffma2(q.x, w[2 * k],     a0);
                a1 = ffma2(q.y, w[2 * k + 1], a1);
            }
            float2 f0 = upk(a0), f1 = upk(a1);
            out[(size_t)(n0 + j) * 256 + t] = (f0.x + f0.y) + (f1.x + f1.y);
        }
        __syncthreads();
    }
}

// ---------- edge aggregation: one warp per target node, atomic-free, f32x2, prefetch-2 ----------
__global__ void k_edge_agg(const float* __restrict__ w1attr, const float* __restrict__ b1,
                           const float* __restrict__ g, const float* __restrict__ be, int N) {
    int warp = (blockIdx.x * blockDim.x + threadIdx.x) >> 5;
    int lane = threadIdx.x & 31;
    if (warp >= N) return;
    int n = warp;
    int s0 = g_off[n], cnt = g_off[n + 1] - s0;

    float4 a4 = ((const float4*)(g_AB + (size_t)n * 256))[lane];
    float4 bb = ((const float4*)b1)[lane];
    u64 base0 = pk(a4.x + bb.x, a4.y + bb.y);
    u64 base1 = pk(a4.z + bb.z, a4.w + bb.w);
    float4 gg4 = ((const float4*)g)[lane];
    float4 ee4 = ((const float4*)be)[lane];
    u64 gp0 = pk(gg4.x, gg4.y), gp1 = pk(gg4.z, gg4.w);
    u64 ep0 = pk(ee4.x, ee4.y), ep1 = pk(ee4.z, ee4.w);
    u64 wa[5][2];
#pragma unroll
    for (int k = 0; k < 5; k++) {
        float4 wk = ((const float4*)(w1attr + k * 128))[lane];
        wa[k][0] = pk(wk.x, wk.y);
        wa[k][1] = pk(wk.z, wk.w);
    }

    u64 acc0 = 0, acc1 = 0;
    ulonglong2 B[2];
    float4 A4[2];
    float  A1[2];

    auto pf = [&](int i, int st) {
        int r = __ldg(&g_srcS[i]);
        B[st]  = __ldg((const ulonglong2*)(g_AB + (size_t)r * 256 + 128) + lane);
        A4[st] = __ldg(&g_attr4[i]);
        A1[st] = __ldg(&g_attr1[i]);
    };
    if (cnt > 0) pf(s0, 0);
    if (cnt > 1) pf(s0 + 1, 1);

    for (int i = 0; i < cnt; i++) {
        int st = i & 1;
        ulonglong2 b = B[st];
        float4 at = A4[st];
        float  a1 = A1[st];
        if (i + 2 < cnt) pf(s0 + i + 2, st);

        u64 p0 = fadd2(base0, b.x);
        u64 p1 = fadd2(base1, b.y);
        u64 c;
        c = pk(at.x, at.x); p0 = ffma2(c, wa[0][0], p0); p1 = ffma2(c, wa[0][1], p1);
        c = pk(at.y, at.y); p0 = ffma2(c, wa[1][0], p0); p1 = ffma2(c, wa[1][1], p1);
        c = pk(at.z, at.z); p0 = ffma2(c, wa[2][0], p0); p1 = ffma2(c, wa[2][1], p1);
        c = pk(at.w, at.w); p0 = ffma2(c, wa[3][0], p0); p1 = ffma2(c, wa[3][1], p1);
        c = pk(a1,  a1 );   p0 = ffma2(c, wa[4][0], p0); p1 = ffma2(c, wa[4][1], p1);

        // warp LN over 128 channels
        u64 sp = fadd2(p0, p1);
        float2 sf = upk(sp);
        float s1 = sf.x + sf.y;
        u64 sq = ffma2(p0, p0, fmul2(p1, p1));
        float2 qf = upk(sq);
        float s2 = qf.x + qf.y;
#pragma unroll
        for (int o = 16; o; o >>= 1) {
            s1 += __shfl_xor_sync(0xffffffffu, s1, o);
            s2 += __shfl_xor_sync(0xffffffffu, s2, o);
        }
        float m = s1 * (1.f / 128.f);
        float var = s2 * (1.f / 128.f) - m * m;
        float rstd = rsqrtf(var + 1e-5f);
        u64 nm = pk(-m, -m), rs = pk(rstd, rstd);
        u64 v0 = ffma2(fmul2(fadd2(p0, nm), rs), gp0, ep0);
        u64 v1 = ffma2(fmul2(fadd2(p1, nm), rs), gp1, ep1);
        float2 x0 = upk(v0), x1 = upk(v1);
        acc0 = fadd2(acc0, pk(siluf(x0.x), siluf(x0.y)));
        acc1 = fadd2(acc1, pk(siluf(x1.x), siluf(x1.y)));
    }
    float2 r0 = upk(acc0), r1 = upk(acc1);
    ((float4*)(g_S + (size_t)n * 128))[lane] = make_float4(r0.x, r0.y, r1.x, r1.y);
}

// ---------- decoder: out = x[:, :6] + MLP(h) ----------
__global__ void k_decoder(const float* __restrict__ x,
                          const float* __restrict__ w1, const float* __restrict__ b1,
                          const float* __restrict__ w2, const float* __restrict__ b2,
                          const float* __restrict__ w3, const float* __restrict__ b3,
                          float* __restrict__ out, int N) {
    int t = threadIdx.x;
    u64 w1p[64];
#pragma unroll
    for (int j = 0; j < 64; j++) w1p[j] = pk(w1[(2 * j) * 128 + t], w1[(2 * j + 1) * 128 + t]);
    float b1t = b1[t];
    float b2t = (t < 64) ? b2[t] : 0.f;
    float b3t = (t < 6) ? b3[t] : 0.f;
    __shared__ __align__(16) float sh[128];
    __shared__ __align__(16) float sd1[128];
    __shared__ __align__(16) float sd2[64];
    __shared__ float sw2[128 * 64];
    __shared__ float sw3[64 * 6];
    for (int i = t; i < 128 * 64; i += blockDim.x) sw2[i] = w2[i];
    for (int i = t; i < 64 * 6; i += blockDim.x) sw3[i] = w3[i];
    __syncthreads();
    for (int n = blockIdx.x; n < N; n += gridDim.x) {
        sh[t] = g_h[(size_t)n * 128 + t];
        __syncthreads();
        u64 a0 = 0, a1 = 0;
        const ulonglong2* h2 = (const ulonglong2*)sh;
#pragma unroll
        for (int k = 0; k < 32; k++) {
            ulonglong2 q = h2[k];
            a0 = ffma2(q.x, w1p[2 * k],     a0);
            a1 = ffma2(q.y, w1p[2 * k + 1], a1);
        }
        float2 f0 = upk(a0), f1 = upk(a1);
        sd1[t] = siluf(b1t + (f0.x + f0.y) + (f1.x + f1.y));
        __syncthreads();
        if (t < 64) {
            float a2 = b2t;
#pragma unroll
            for (int k = 0; k < 128; k++) a2 = fmaf(sd1[k], sw2[k * 64 + t], a2);
            sd2[t] = siluf(a2);
        }
        __syncthreads();
        if (t < 6) {
            float a3 = b3t;
#pragma unroll
            for (int k = 0; k < 64; k++) a3 = fmaf(sd2[k], sw3[k * 6 + t], a3);
            out[(size_t)n * 6 + t] = x[(size_t)n * 7 + t] + a3;
        }
        __syncthreads();
    }
}

extern "C" void kernel_launch(void* const* d_in, const int* in_sizes, int n_in,
                              void* d_out, int out_size) {
    const float* x      = (const float*)d_in[0];
    const float* pos    = (const float*)d_in[1];
    const void*  eidx   = d_in[2];
    const float* enc_w1 = (const float*)d_in[3];
    const float* enc_b1 = (const float*)d_in[4];
    const float* enc_g  = (const float*)d_in[5];
    const float* enc_be = (const float*)d_in[6];
    const float* enc_w2 = (const float*)d_in[7];
    const float* enc_b2 = (const float*)d_in[8];
    const float* e_w1   = (const float*)d_in[9];
    const float* e_b1   = (const float*)d_in[10];
    const float* e_g    = (const float*)d_in[11];
    const float* e_be   = (const float*)d_in[12];
    const float* e_w2   = (const float*)d_in[13];
    const float* e_b2   = (const float*)d_in[14];
    const float* n_w1   = (const float*)d_in[15];
    const float* n_b1   = (const float*)d_in[16];
    const float* n_g    = (const float*)d_in[17];
    const float* n_be   = (const float*)d_in[18];
    const float* n_w2   = (const float*)d_in[19];
    const float* n_b2   = (const float*)d_in[20];
    const float* ln_g   = (const float*)d_in[21];
    const float* ln_b   = (const float*)d_in[22];
    const float* dec_w1 = (const float*)d_in[23];
    const float* dec_b1 = (const float*)d_in[24];
    const float* dec_w2 = (const float*)d_in[25];
    const float* dec_b2 = (const float*)d_in[26];
    const float* dec_w3 = (const float*)d_in[27];
    const float* dec_b3 = (const float*)d_in[28];
    float* out = (float*)d_out;

    int N = in_sizes[0] / 7;
    long long E = (long long)in_sizes[2] / 2;
    int nchunks = (N + 1023) / 1024;

    float *p_h, *p_AB, *p_S, *p_aggr, *p_part, *p_u;
    cudaGetSymbolAddress((void**)&p_h,    g_h);
    cudaGetSymbolAddress((void**)&p_AB,   g_AB);
    cudaGetSymbolAddress((void**)&p_S,    g_S);
    cudaGetSymbolAddress((void**)&p_aggr, g_aggr);
    cudaGetSymbolAddress((void**)&p_part, g_part);
    cudaGetSymbolAddress((void**)&p_u,    g_u);

    const int GB  = 444;   // k_gemm grid (3 blocks/SM, 4 nodes/iter, grid-stride)
    const int GAB = 296;   // k_gemmAB grid
    unsigned eg = (unsigned)((E + 255) / 256);

    // dtype detect + counting sort of edges by target + physics features
    k_detect<<<1, 256>>>((const int*)eidx, 2 * E);
    k_zero_cnt<<<(N + 256) / 256, 256>>>(N);
    k_hist<<<eg, 256>>>(eidx, E);
    k_scanA<<<nchunks, 256>>>(N);
    k_scanB<<<1, 64>>>(nchunks);
    k_scanC<<<nchunks, 1024>>>(N, nchunks);
    k_scatter<<<eg, 256>>>(eidx, pos, E);

    k_encoder<<<GB, 128>>>(x, enc_w1, enc_b1, enc_g, enc_be, enc_w2, enc_b2, N);

    unsigned aggGrid = (unsigned)((N + 7) / 8);  // one warp per node, 256-thread blocks
    for (int l = 0; l < 3; l++) {
        const float* W1 = e_w1 + (size_t)l * 261 * 128;
        // [A|B] = h @ W1[0:256] (fused, into g_AB stride 256)
        k_gemmAB<<<GAB, 256>>>(p_h, W1, p_AB, N);
        // per-target segment aggregation (atomic-free)
        k_edge_agg<<<aggGrid, 256>>>(W1 + 256 * 128, e_b1 + l * 128,
                                     e_g + l * 128, e_be + l * 128, N);
        // aggr = S @ e_w2 + deg * e_b2
        k_gemm<1><<<GB, 128>>>(p_S, e_w2 + (size_t)l * 128 * 128, p_aggr, 128, 0,
                               e_b2 + l * 128, nullptr, nullptr, N);
        // node MLP: part = h @ n_w1[:128]; u = silu(ln(part + aggr @ n_w1[128:] + b1))
        k_gemm<0><<<GB, 128>>>(p_h, n_w1 + (size_t)l * 256 * 128, p_part, 128, 0,
                               nullptr, nullptr, nullptr, N);
        k_gemm<2><<<GB, 128>>>(p_aggr, n_w1 + (size_t)l * 256 * 128 + 128 * 128, p_u, 128, 0,
                               n_b1 + l * 128, n_g + l * 128, n_be + l * 128, N);
        // h = ln(h + u @ n_w2 + b2, ln_g, ln_b)
        k_gemm<3><<<GB, 128>>>(p_u, n_w2 + (size_t)l * 128 * 128, p_h, 128, 0,
                               n_b2 + l * 128, ln_g + l * 128, ln_b + l * 128, N);
    }

    k_decoder<<<GB, 128>>>(x, dec_w1, dec_b1, dec_w2, dec_b2, dec_w3, dec_b3, out, N);
}